// round 8
// baseline (speedup 1.0000x reference)
#include <cuda_runtime.h>
#include <math.h>

// ---------------------------------------------------------------------------
// SimpleVQAutoEncoder forward, exact fp32, XLA-CPU-rounding-aligned.
//  - erf: XLA MaterializeErfApproximationF32: clamp x to [-4,4],
//         erf = x * P(x2) / Q(x2), alpha[7]/beta[5], strict mul/add Horner
//         (acc starts at 0), IEEE division. (R4's failure traced to a
//         spurious 6th beta coefficient, not to the clamped-poly shape.)
//  - gelu: x * (erf(x/sqrt2) + 1) / 2, IEEE division by sqrt2
//  - convs: sequential fma accumulate, Eigen-NHWC im2col k-order (ky,kx,ic;
//           ic innermost), bias added after
//  - VQ: dist = fl(fl(x2 - 2*xc) + c2); xc sequential fma over d;
//        x2/c2 mul-then-add sequential; first-min argmin
//  - straight-through: q_out = fl(x + fl(q - x))
// f32x2 packed FMA in k3/k4 (bit-identical per lane).
// Outputs in d_out (fp32): image | indices | commit_loss
// ---------------------------------------------------------------------------

#define BATCH 64
typedef unsigned long long ull;

__device__ float g_h1[BATCH * 16 * 128 * 128];
__device__ float g_h2[BATCH * 32 * 64 * 64];
__device__ float g_q [BATCH * 32 * 64 * 64];
__device__ float g_h3[BATCH * 16 * 128 * 128];
__device__ float g_partial[1024];

// XLA f32 erf: single rational approximation, clamp to [-4,4].
// alpha[7], beta[5]; Horner acc starts at 0; separate mul/add; IEEE div.
__device__ __forceinline__ float erf_xla(float x) {
    const float w  = fminf(fmaxf(x, -4.0f), 4.0f);
    const float x2 = __fmul_rn(w, w);

    float p = -2.72614225801306e-10f;               // fl(0*x2 + a0) = a0
    p = __fadd_rn(__fmul_rn(p, x2),  2.77068142495902e-08f);
    p = __fadd_rn(__fmul_rn(p, x2), -2.10102402082508e-06f);
    p = __fadd_rn(__fmul_rn(p, x2), -5.69250639462346e-05f);
    p = __fadd_rn(__fmul_rn(p, x2), -7.34990630326855e-04f);
    p = __fadd_rn(__fmul_rn(p, x2), -2.95459980854025e-03f);
    p = __fadd_rn(__fmul_rn(p, x2), -1.60960333262415e-02f);
    p = __fmul_rn(w, p);

    float q = -1.45660718464996e-05f;               // fl(0*x2 + b0) = b0
    q = __fadd_rn(__fmul_rn(q, x2), -2.13374055278905e-04f);
    q = __fadd_rn(__fmul_rn(q, x2), -1.68282697438203e-03f);
    q = __fadd_rn(__fmul_rn(q, x2), -7.37332916720468e-03f);
    q = __fadd_rn(__fmul_rn(q, x2), -1.42647390514189e-02f);

    return __fdiv_rn(p, q);
}

__device__ __forceinline__ float gelu_exact(float v) {
    // jax.nn.gelu(approximate=False): x * (erf(x/sqrt2) + 1) / 2
    const float t = __fdiv_rn(v, 1.41421356237309504880f);
    const float e = erf_xla(t);
    return 0.5f * __fmul_rn(v, __fadd_rn(e, 1.0f));
}

__device__ __forceinline__ ull pk2(float lo, float hi) {
    ull r; asm("mov.b64 %0, {%1, %2};" : "=l"(r) : "f"(lo), "f"(hi)); return r;
}
__device__ __forceinline__ void upk2(ull v, float& lo, float& hi) {
    asm("mov.b64 {%0, %1}, %2;" : "=f"(lo), "=f"(hi) : "l"(v));
}
__device__ __forceinline__ ull fma2(ull a, ull b, ull c) {
    ull r; asm("fma.rn.f32x2 %0, %1, %2, %3;" : "=l"(r) : "l"(a), "l"(b), "l"(c));
    return r;
}

// ---------------------------------------------------------------------------
// K1: conv1 (1->16, 3x3 SAME) + bias-after + maxpool2 + gelu. [B,16,128,128]
// ---------------------------------------------------------------------------
__global__ void k1_conv1_pool_gelu(const float* __restrict__ x,
                                   const float* __restrict__ w1,
                                   const float* __restrict__ b1,
                                   float* __restrict__ h1) {
    __shared__ float xs[34][35];
    __shared__ float ws[16 * 9];
    __shared__ float bs[16];

    const int b   = blockIdx.z;
    const int px0 = blockIdx.x * 16, py0 = blockIdx.y * 16;
    const int t   = threadIdx.y * 16 + threadIdx.x;

    if (t < 144) ws[t] = w1[t];
    if (t < 16)  bs[t] = b1[t];

    const float* xb = x + (size_t)b * 65536;
    for (int i = t; i < 34 * 34; i += 256) {
        int r = i / 34, c = i % 34;
        int gy = 2 * py0 - 1 + r, gx = 2 * px0 - 1 + c;
        float v = 0.0f;
        if (gy >= 0 && gy < 256 && gx >= 0 && gx < 256) v = xb[gy * 256 + gx];
        xs[r][c] = v;
    }
    __syncthreads();

    const int ty = threadIdx.y, tx = threadIdx.x;
    for (int oc = 0; oc < 16; oc++) {
        float wv[9];
        #pragma unroll
        for (int j = 0; j < 9; j++) wv[j] = ws[oc * 9 + j];
        const float bias = bs[oc];
        float m = -3.4e38f;
        #pragma unroll
        for (int dy = 0; dy < 2; dy++)
        #pragma unroll
        for (int dx = 0; dx < 2; dx++) {
            float a = 0.0f;
            #pragma unroll
            for (int ky = 0; ky < 3; ky++)
            #pragma unroll
            for (int kx = 0; kx < 3; kx++)
                a = fmaf(xs[2 * ty + dy + ky][2 * tx + dx + kx], wv[ky * 3 + kx], a);
            m = fmaxf(m, __fadd_rn(a, bias));
        }
        h1[(((size_t)b * 16 + oc) * 128 + (py0 + ty)) * 128 + (px0 + tx)] = gelu_exact(m);
    }
}

// ---------------------------------------------------------------------------
// K2: conv2 (16->32), Eigen im2col k-order (ky,kx,ic; ic innermost),
// bias-after + maxpool2.
// ---------------------------------------------------------------------------
__global__ void k2_conv2_pool(const float* __restrict__ h1,
                              const float* __restrict__ w2,
                              const float* __restrict__ b2,
                              float* __restrict__ h2) {
    __shared__ float hs[16][18][18];
    __shared__ float ws[32 * 16 * 9];
    __shared__ float bs[32];

    const int b   = blockIdx.z;
    const int px0 = blockIdx.x * 8, py0 = blockIdx.y * 8;
    const int t   = threadIdx.x;

    for (int i = t; i < 4608; i += 256) ws[i] = w2[i];
    if (t < 32) bs[t] = b2[t];

    const float* hb = h1 + (size_t)b * 16 * 16384;
    for (int i = t; i < 16 * 18 * 18; i += 256) {
        int ic = i / 324, rem = i % 324;
        int r = rem / 18, c = rem % 18;
        int gy = 2 * py0 - 1 + r, gx = 2 * px0 - 1 + c;
        float v = 0.0f;
        if (gy >= 0 && gy < 128 && gx >= 0 && gx < 128) v = hb[ic * 16384 + gy * 128 + gx];
        hs[ic][r][c] = v;
    }
    __syncthreads();

    const int s  = t & 63, g = t >> 6;
    const int px = s & 7, py = s >> 3;

    float acc[8][4];
    #pragma unroll
    for (int i = 0; i < 8; i++) {
        acc[i][0] = 0.f; acc[i][1] = 0.f; acc[i][2] = 0.f; acc[i][3] = 0.f;
    }

    #pragma unroll
    for (int ky = 0; ky < 3; ky++)
    #pragma unroll
    for (int kx = 0; kx < 3; kx++) {
        for (int ic = 0; ic < 16; ic++) {          // ic innermost (NHWC im2col)
            const float u00 = hs[ic][2 * py + 0 + ky][2 * px + 0 + kx];
            const float u01 = hs[ic][2 * py + 0 + ky][2 * px + 1 + kx];
            const float u10 = hs[ic][2 * py + 1 + ky][2 * px + 0 + kx];
            const float u11 = hs[ic][2 * py + 1 + ky][2 * px + 1 + kx];
            #pragma unroll
            for (int i = 0; i < 8; i++) {
                const float w = ws[((g * 8 + i) * 16 + ic) * 9 + ky * 3 + kx];
                acc[i][0] = fmaf(u00, w, acc[i][0]);
                acc[i][1] = fmaf(u01, w, acc[i][1]);
                acc[i][2] = fmaf(u10, w, acc[i][2]);
                acc[i][3] = fmaf(u11, w, acc[i][3]);
            }
        }
    }

    #pragma unroll
    for (int i = 0; i < 8; i++) {
        const int oc = g * 8 + i;
        const float bb = bs[oc];
        float m = fmaxf(fmaxf(__fadd_rn(acc[i][0], bb), __fadd_rn(acc[i][1], bb)),
                        fmaxf(__fadd_rn(acc[i][2], bb), __fadd_rn(acc[i][3], bb)));
        h2[(((size_t)b * 32 + oc) * 64 + (py0 + py)) * 64 + (px0 + px)] = m;
    }
}

// ---------------------------------------------------------------------------
// K3: VQ. dist = fl(fl(x2-2xc)+c2); xc sequential fma over d;
// x2/c2 mul-then-add sequential; first-min argmin; q_out = fl(x + fl(q-x)).
// grid 1024, block 256, dyn smem = 32*512*4 + 512*4 = 67584 B.
// ---------------------------------------------------------------------------
__global__ void k3_vq(const float* __restrict__ h2,
                      const float* __restrict__ cb,
                      float* __restrict__ q,
                      float* __restrict__ outF,
                      float* __restrict__ partial) {
    extern __shared__ float sm[];
    float* scbT = sm;             // [32][512]
    float* sc2  = sm + 32 * 512;  // [512]
    const int t = threadIdx.x;

    for (int i = t; i < 32 * 512; i += 256) {
        int d = i >> 9, k = i & 511;
        scbT[i] = cb[k * 32 + d];
    }
    for (int k = t; k < 512; k += 256) {
        const float* c = cb + k * 32;
        float s = 0.0f;
        #pragma unroll
        for (int d = 0; d < 32; d++) s = __fadd_rn(s, __fmul_rn(c[d], c[d]));
        sc2[k] = s;
    }
    __syncthreads();

    const int v = blockIdx.x * 256 + t;
    const int b = v >> 12, p = v & 4095;
    const float* hb = h2 + ((size_t)b * 32) * 4096 + p;

    float xv[32];
    float x2 = 0.0f;
    #pragma unroll
    for (int d = 0; d < 32; d++) {
        xv[d] = hb[(size_t)d * 4096];
        x2 = __fadd_rn(x2, __fmul_rn(xv[d], xv[d]));
    }

    float best = 3.4e38f;
    int bi = 0;
    for (int k0 = 0; k0 < 512; k0 += 8) {
        ull a0 = 0, a1 = 0, a2 = 0, a3 = 0;
        #pragma unroll
        for (int d = 0; d < 32; d++) {       // sequential over d per lane
            const ull xs = pk2(xv[d], xv[d]);
            const ull* row = (const ull*)(scbT + d * 512 + k0);
            a0 = fma2(row[0], xs, a0);
            a1 = fma2(row[1], xs, a1);
            a2 = fma2(row[2], xs, a2);
            a3 = fma2(row[3], xs, a3);
        }
        float xc[8];
        upk2(a0, xc[0], xc[1]); upk2(a1, xc[2], xc[3]);
        upk2(a2, xc[4], xc[5]); upk2(a3, xc[6], xc[7]);
        #pragma unroll
        for (int j = 0; j < 8; j++) {
            const float dst = __fadd_rn(__fsub_rn(x2, __fmul_rn(2.0f, xc[j])), sc2[k0 + j]);
            if (dst < best) { best = dst; bi = k0 + j; }  // first-min
        }
    }

    const float* c = cb + bi * 32;
    float* qb = q + ((size_t)b * 32) * 4096 + p;
    float err = 0.0f;
    #pragma unroll
    for (int d = 0; d < 32; d++) {
        const float qd = c[d];
        const float e  = __fsub_rn(qd, xv[d]);
        err = __fadd_rn(err, __fmul_rn(e, e));
        qb[(size_t)d * 4096] = __fadd_rn(xv[d], e);   // fl(x + fl(q-x))
    }
    outF[4194304 + v] = (float)bi;

    __shared__ float red[256];
    red[t] = err;
    __syncthreads();
    #pragma unroll
    for (int s2 = 128; s2 > 0; s2 >>= 1) {
        if (t < s2) red[t] += red[t + s2];
        __syncthreads();
    }
    if (t == 0) partial[blockIdx.x] = red[0];
}

// ---------------------------------------------------------------------------
// K4: upsample2 + conv3 (32->16), (ky,kx,ic) order ic innermost,
// bias-after + gelu. f32x2 over oc pairs. [B,16,128,128]
// ---------------------------------------------------------------------------
__global__ void k4_up_conv3_gelu(const float* __restrict__ q,
                                 const float* __restrict__ w3,
                                 const float* __restrict__ b3,
                                 float* __restrict__ h3) {
    __shared__ float qs[32][10][10];
    __shared__ __align__(8) float wsT[288 * 16];
    __shared__ float bs[16];

    const int b   = blockIdx.z;
    const int ox0 = blockIdx.x * 16, oy0 = blockIdx.y * 16;
    const int t   = threadIdx.y * 16 + threadIdx.x;

    for (int i = t; i < 4608; i += 256) {
        int o = i & 15, j = i >> 4;
        wsT[i] = w3[o * 288 + j];
    }
    if (t < 16) bs[t] = b3[t];

    const int qx0 = (ox0 - 1) >> 1, qy0 = (oy0 - 1) >> 1;
    const float* qbase = q + (size_t)b * 32 * 4096;
    for (int i = t; i < 32 * 100; i += 256) {
        int c = i / 100, rem = i % 100;
        int r = rem / 10, cc = rem % 10;
        int gy = qy0 + r, gx = qx0 + cc;
        float v = 0.0f;
        if (gy >= 0 && gy < 64 && gx >= 0 && gx < 64) v = qbase[c * 4096 + gy * 64 + gx];
        qs[c][r][cc] = v;
    }
    __syncthreads();

    const int ox = ox0 + threadIdx.x, oy = oy0 + threadIdx.y;
    int jr[3], ji[3];
    #pragma unroll
    for (int kk = 0; kk < 3; kk++) {
        jr[kk] = ((oy - 1 + kk) >> 1) - qy0;   // always in [0,9]
        ji[kk] = ((ox - 1 + kk) >> 1) - qx0;
    }

    ull A[8];
    #pragma unroll
    for (int p = 0; p < 8; p++) A[p] = 0;

    #pragma unroll
    for (int ky = 0; ky < 3; ky++)
    #pragma unroll
    for (int kx = 0; kx < 3; kx++) {
        for (int c = 0; c < 32; c++) {           // ic innermost (NHWC im2col)
            const float u = qs[c][jr[ky]][ji[kx]];
            const ull us = pk2(u, u);
            const ull* wrow = (const ull*)(wsT + (c * 9 + ky * 3 + kx) * 16);
            #pragma unroll
            for (int p = 0; p < 8; p++) A[p] = fma2(wrow[p], us, A[p]);
        }
    }

    #pragma unroll
    for (int p = 0; p < 8; p++) {
        float a0, a1;
        upk2(A[p], a0, a1);
        h3[(((size_t)b * 16 + 2 * p + 0) * 128 + oy) * 128 + ox] =
            gelu_exact(__fadd_rn(a0, bs[2 * p + 0]));
        h3[(((size_t)b * 16 + 2 * p + 1) * 128 + oy) * 128 + ox] =
            gelu_exact(__fadd_rn(a1, bs[2 * p + 1]));
    }
}

// ---------------------------------------------------------------------------
// K5: upsample2 + conv4 (16->1), (ky,kx,ic) order, bias-after + clip.
// ---------------------------------------------------------------------------
__global__ void k5_up_conv4_clip(const float* __restrict__ h3,
                                 const float* __restrict__ w4,
                                 const float* __restrict__ b4,
                                 float* __restrict__ outF) {
    __shared__ float hs[16][10][10];
    __shared__ float ws[144];

    const int b   = blockIdx.z;
    const int ox0 = blockIdx.x * 16, oy0 = blockIdx.y * 16;
    const int t   = threadIdx.y * 16 + threadIdx.x;

    if (t < 144) ws[t] = w4[t];

    const int qx0 = (ox0 - 1) >> 1, qy0 = (oy0 - 1) >> 1;
    const float* hb = h3 + (size_t)b * 16 * 16384;
    for (int i = t; i < 1600; i += 256) {
        int c = i / 100, rem = i % 100;
        int r = rem / 10, cc = rem % 10;
        int gy = qy0 + r, gx = qx0 + cc;
        float v = 0.0f;
        if (gy >= 0 && gy < 128 && gx >= 0 && gx < 128) v = hb[c * 16384 + gy * 128 + gx];
        hs[c][r][cc] = v;
    }
    __syncthreads();

    const int ox = ox0 + threadIdx.x, oy = oy0 + threadIdx.y;
    int jr[3], ji[3];
    #pragma unroll
    for (int kk = 0; kk < 3; kk++) {
        jr[kk] = ((oy - 1 + kk) >> 1) - qy0;
        ji[kk] = ((ox - 1 + kk) >> 1) - qx0;
    }

    float a = 0.0f;
    #pragma unroll
    for (int ky = 0; ky < 3; ky++)
    #pragma unroll
    for (int kx = 0; kx < 3; kx++) {
        for (int c = 0; c < 16; c++)             // ic innermost
            a = fmaf(hs[c][jr[ky]][ji[kx]], ws[c * 9 + ky * 3 + kx], a);
    }
    a = __fadd_rn(a, b4[0]);
    a = fminf(fmaxf(a, -1.0f), 1.0f);
    outF[(size_t)b * 65536 + oy * 256 + ox] = a;
}

// ---------------------------------------------------------------------------
// K6: deterministic final reduction of commit loss. (1/2^23 exact.)
// ---------------------------------------------------------------------------
__global__ void k6_loss(const float* __restrict__ partial, float* __restrict__ outF) {
    __shared__ float red[256];
    const int t = threadIdx.x;
    red[t] = ((partial[t] + partial[t + 256]) + (partial[t + 512] + partial[t + 768]));
    __syncthreads();
    #pragma unroll
    for (int s2 = 128; s2 > 0; s2 >>= 1) {
        if (t < s2) red[t] += red[t + s2];
        __syncthreads();
    }
    if (t == 0) outF[4194304 + 262144] = red[0] * (1.0f / 8388608.0f);
}

// ---------------------------------------------------------------------------
extern "C" void kernel_launch(void* const* d_in, const int* in_sizes, int n_in,
                              void* d_out, int out_size) {
    const float* x  = (const float*)d_in[0];
    const float* w1 = (const float*)d_in[1];
    const float* b1 = (const float*)d_in[2];
    const float* w2 = (const float*)d_in[3];
    const float* b2 = (const float*)d_in[4];
    const float* cb = (const float*)d_in[5];
    const float* w3 = (const float*)d_in[6];
    const float* b3 = (const float*)d_in[7];
    const float* w4 = (const float*)d_in[8];
    const float* b4 = (const float*)d_in[9];
    float* outF = (float*)d_out;

    float *h1, *h2, *q, *h3, *partial;
    cudaGetSymbolAddress((void**)&h1, g_h1);
    cudaGetSymbolAddress((void**)&h2, g_h2);
    cudaGetSymbolAddress((void**)&q,  g_q);
    cudaGetSymbolAddress((void**)&h3, g_h3);
    cudaGetSymbolAddress((void**)&partial, g_partial);

    cudaFuncSetAttribute(k3_vq, cudaFuncAttributeMaxDynamicSharedMemorySize, 67584);

    k1_conv1_pool_gelu<<<dim3(8, 8, BATCH), dim3(16, 16)>>>(x, w1, b1, h1);
    k2_conv2_pool<<<dim3(8, 8, BATCH), 256>>>(h1, w2, b2, h2);
    k3_vq<<<1024, 256, 67584>>>(h2, cb, q, outF, partial);
    k4_up_conv3_gelu<<<dim3(8, 8, BATCH), dim3(16, 16)>>>(q, w3, b3, h3);
    k5_up_conv4_clip<<<dim3(16, 16, BATCH), dim3(16, 16)>>>(h3, w4, b4, outF);
    k6_loss<<<1, 256>>>(partial, outF);
}

// round 9
// speedup vs baseline: 1.6158x; 1.6158x over previous
#include <cuda_runtime.h>
#include <math.h>

// ---------------------------------------------------------------------------
// SimpleVQAutoEncoder forward. k1/k2/k3 bit-exact (XLA-CPU-aligned, decide VQ
// indices); k4/k5 downstream of VQ -> numerics re-associated for speed
// (phase-decomposed upsample-conv with combined weights).
// Outputs in d_out (fp32): image | indices | commit_loss
// ---------------------------------------------------------------------------

#define BATCH 64
typedef unsigned long long ull;

__device__ float g_h1[BATCH * 16 * 128 * 128];
__device__ float g_h2[BATCH * 32 * 64 * 64];
__device__ float g_q [BATCH * 32 * 64 * 64];
__device__ float g_h3[BATCH * 16 * 128 * 128];
__device__ float g_partial[1024];

// XLA f32 erf: single rational approximation, clamp to [-4,4]. (exact path)
__device__ __forceinline__ float erf_xla(float x) {
    const float w  = fminf(fmaxf(x, -4.0f), 4.0f);
    const float x2 = __fmul_rn(w, w);
    float p = -2.72614225801306e-10f;
    p = __fadd_rn(__fmul_rn(p, x2),  2.77068142495902e-08f);
    p = __fadd_rn(__fmul_rn(p, x2), -2.10102402082508e-06f);
    p = __fadd_rn(__fmul_rn(p, x2), -5.69250639462346e-05f);
    p = __fadd_rn(__fmul_rn(p, x2), -7.34990630326855e-04f);
    p = __fadd_rn(__fmul_rn(p, x2), -2.95459980854025e-03f);
    p = __fadd_rn(__fmul_rn(p, x2), -1.60960333262415e-02f);
    p = __fmul_rn(w, p);
    float q = -1.45660718464996e-05f;
    q = __fadd_rn(__fmul_rn(q, x2), -2.13374055278905e-04f);
    q = __fadd_rn(__fmul_rn(q, x2), -1.68282697438203e-03f);
    q = __fadd_rn(__fmul_rn(q, x2), -7.37332916720468e-03f);
    q = __fadd_rn(__fmul_rn(q, x2), -1.42647390514189e-02f);
    return __fdiv_rn(p, q);
}

__device__ __forceinline__ float gelu_exact(float v) {
    const float t = __fdiv_rn(v, 1.41421356237309504880f);
    const float e = erf_xla(t);
    return 0.5f * __fmul_rn(v, __fadd_rn(e, 1.0f));
}

// Fast gelu for image-only path (k4): same poly, relaxed rounding.
__device__ __forceinline__ float gelu_fast(float v) {
    const float t = v * 0.70710678118654752440f;
    return 0.5f * v * (1.0f + erf_xla(t));
}

__device__ __forceinline__ ull pk2(float lo, float hi) {
    ull r; asm("mov.b64 %0, {%1, %2};" : "=l"(r) : "f"(lo), "f"(hi)); return r;
}
__device__ __forceinline__ void upk2(ull v, float& lo, float& hi) {
    asm("mov.b64 {%0, %1}, %2;" : "=f"(lo), "=f"(hi) : "l"(v));
}
__device__ __forceinline__ ull fma2(ull a, ull b, ull c) {
    ull r; asm("fma.rn.f32x2 %0, %1, %2, %3;" : "=l"(r) : "l"(a), "l"(b), "l"(c));
    return r;
}

// ---------------------------------------------------------------------------
// K1: conv1 (1->16) + bias-after + maxpool2 + gelu (EXACT). [B,16,128,128]
// ---------------------------------------------------------------------------
__global__ void k1_conv1_pool_gelu(const float* __restrict__ x,
                                   const float* __restrict__ w1,
                                   const float* __restrict__ b1,
                                   float* __restrict__ h1) {
    __shared__ float xs[34][35];
    __shared__ float ws[16 * 9];
    __shared__ float bs[16];

    const int b   = blockIdx.z;
    const int px0 = blockIdx.x * 16, py0 = blockIdx.y * 16;
    const int t   = threadIdx.y * 16 + threadIdx.x;

    if (t < 144) ws[t] = w1[t];
    if (t < 16)  bs[t] = b1[t];

    const float* xb = x + (size_t)b * 65536;
    for (int i = t; i < 34 * 34; i += 256) {
        int r = i / 34, c = i % 34;
        int gy = 2 * py0 - 1 + r, gx = 2 * px0 - 1 + c;
        float v = 0.0f;
        if (gy >= 0 && gy < 256 && gx >= 0 && gx < 256) v = xb[gy * 256 + gx];
        xs[r][c] = v;
    }
    __syncthreads();

    const int ty = threadIdx.y, tx = threadIdx.x;
    for (int oc = 0; oc < 16; oc++) {
        float wv[9];
        #pragma unroll
        for (int j = 0; j < 9; j++) wv[j] = ws[oc * 9 + j];
        const float bias = bs[oc];
        float m = -3.4e38f;
        #pragma unroll
        for (int dy = 0; dy < 2; dy++)
        #pragma unroll
        for (int dx = 0; dx < 2; dx++) {
            float a = 0.0f;
            #pragma unroll
            for (int ky = 0; ky < 3; ky++)
            #pragma unroll
            for (int kx = 0; kx < 3; kx++)
                a = fmaf(xs[2 * ty + dy + ky][2 * tx + dx + kx], wv[ky * 3 + kx], a);
            m = fmaxf(m, __fadd_rn(a, bias));
        }
        h1[(((size_t)b * 16 + oc) * 128 + (py0 + ty)) * 128 + (px0 + tx)] = gelu_exact(m);
    }
}

// ---------------------------------------------------------------------------
// K2: conv2 (16->32), EXACT per-oc chain (ky,kx,ic innermost), f32x2 over
// oc pairs (each lane = one oc chain, bit-identical). bias-after + pool.
// ---------------------------------------------------------------------------
__global__ void k2_conv2_pool(const float* __restrict__ h1,
                              const float* __restrict__ w2,
                              const float* __restrict__ b2,
                              float* __restrict__ h2) {
    __shared__ float hs[16][18][18];                 // 20736 B
    __shared__ __align__(8) float wsT[144 * 32];     // 18432 B, [j][oc]
    __shared__ float bs[32];

    const int b   = blockIdx.z;
    const int px0 = blockIdx.x * 8, py0 = blockIdx.y * 8;
    const int t   = threadIdx.x;

    // transpose weights: wsT[j*32+o] = w2[o*144 + j], j = ic*9+ky*3+kx
    for (int i = t; i < 4608; i += 256) {
        int o = i & 31, j = i >> 5;
        wsT[j * 32 + o] = w2[o * 144 + j];
    }
    if (t < 32) bs[t] = b2[t];

    const float* hb = h1 + (size_t)b * 16 * 16384;
    for (int i = t; i < 16 * 18 * 18; i += 256) {
        int ic = i / 324, rem = i % 324;
        int r = rem / 18, c = rem % 18;
        int gy = 2 * py0 - 1 + r, gx = 2 * px0 - 1 + c;
        float v = 0.0f;
        if (gy >= 0 && gy < 128 && gx >= 0 && gx < 128) v = hb[ic * 16384 + gy * 128 + gx];
        hs[ic][r][c] = v;
    }
    __syncthreads();

    const int s  = t & 63, g = t >> 6;   // g: oc-group (8 oc = 4 pairs)
    const int px = s & 7, py = s >> 3;

    ull acc[4][4];
    #pragma unroll
    for (int p = 0; p < 4; p++)
        #pragma unroll
        for (int wv = 0; wv < 4; wv++) acc[p][wv] = 0;

    #pragma unroll
    for (int ky = 0; ky < 3; ky++)
    #pragma unroll
    for (int kx = 0; kx < 3; kx++) {
        for (int ic = 0; ic < 16; ic++) {          // ic innermost
            const float u00 = hs[ic][2 * py + 0 + ky][2 * px + 0 + kx];
            const float u01 = hs[ic][2 * py + 0 + ky][2 * px + 1 + kx];
            const float u10 = hs[ic][2 * py + 1 + ky][2 * px + 0 + kx];
            const float u11 = hs[ic][2 * py + 1 + ky][2 * px + 1 + kx];
            const ull s00 = pk2(u00, u00), s01 = pk2(u01, u01);
            const ull s10 = pk2(u10, u10), s11 = pk2(u11, u11);
            const int j = ic * 9 + ky * 3 + kx;
            const ull* wrow = (const ull*)(wsT + j * 32) + g * 4;
            #pragma unroll
            for (int p = 0; p < 4; p++) {
                const ull wp = wrow[p];
                acc[p][0] = fma2(wp, s00, acc[p][0]);
                acc[p][1] = fma2(wp, s01, acc[p][1]);
                acc[p][2] = fma2(wp, s10, acc[p][2]);
                acc[p][3] = fma2(wp, s11, acc[p][3]);
            }
        }
    }

    #pragma unroll
    for (int p = 0; p < 4; p++) {
        float a0[4], a1[4];
        #pragma unroll
        for (int wv = 0; wv < 4; wv++) upk2(acc[p][wv], a0[wv], a1[wv]);
        const int oc0 = g * 8 + 2 * p, oc1 = oc0 + 1;
        const float bb0 = bs[oc0], bb1 = bs[oc1];
        float m0 = fmaxf(fmaxf(__fadd_rn(a0[0], bb0), __fadd_rn(a0[1], bb0)),
                         fmaxf(__fadd_rn(a0[2], bb0), __fadd_rn(a0[3], bb0)));
        float m1 = fmaxf(fmaxf(__fadd_rn(a1[0], bb1), __fadd_rn(a1[1], bb1)),
                         fmaxf(__fadd_rn(a1[2], bb1), __fadd_rn(a1[3], bb1)));
        h2[(((size_t)b * 32 + oc0) * 64 + (py0 + py)) * 64 + (px0 + px)] = m0;
        h2[(((size_t)b * 32 + oc1) * 64 + (py0 + py)) * 64 + (px0 + px)] = m1;
    }
}

// ---------------------------------------------------------------------------
// K3: VQ (EXACT per vector). 2 vectors per thread to amortize codebook LDS.
// grid 512, block 256, dyn smem 67584 B.
// ---------------------------------------------------------------------------
__global__ void __launch_bounds__(256, 2)
k3_vq(const float* __restrict__ h2,
      const float* __restrict__ cb,
      float* __restrict__ q,
      float* __restrict__ outF,
      float* __restrict__ partial) {
    extern __shared__ float sm[];
    float* scbT = sm;             // [32][512]
    float* sc2  = sm + 32 * 512;  // [512]
    const int t = threadIdx.x;

    for (int i = t; i < 32 * 512; i += 256) {
        int d = i >> 9, k = i & 511;
        scbT[i] = cb[k * 32 + d];
    }
    for (int k = t; k < 512; k += 256) {
        const float* c = cb + k * 32;
        float s = 0.0f;
        #pragma unroll
        for (int d = 0; d < 32; d++) s = __fadd_rn(s, __fmul_rn(c[d], c[d]));
        sc2[k] = s;
    }
    __syncthreads();

    const int vA = blockIdx.x * 256 + t;        // [0, 131072)
    const int vB = vA + 131072;
    const int bA = vA >> 12, pA = vA & 4095;
    const int bB = vB >> 12, pB = vB & 4095;
    const float* hA = h2 + ((size_t)bA * 32) * 4096 + pA;
    const float* hB = h2 + ((size_t)bB * 32) * 4096 + pB;

    float xvA[32], xvB[32];
    float x2A = 0.0f, x2B = 0.0f;
    #pragma unroll
    for (int d = 0; d < 32; d++) {
        xvA[d] = hA[(size_t)d * 4096];
        xvB[d] = hB[(size_t)d * 4096];
        x2A = __fadd_rn(x2A, __fmul_rn(xvA[d], xvA[d]));
        x2B = __fadd_rn(x2B, __fmul_rn(xvB[d], xvB[d]));
    }

    float bestA = 3.4e38f, bestB = 3.4e38f;
    int biA = 0, biB = 0;
    for (int k0 = 0; k0 < 512; k0 += 8) {
        ull aA0 = 0, aA1 = 0, aA2 = 0, aA3 = 0;
        ull aB0 = 0, aB1 = 0, aB2 = 0, aB3 = 0;
        #pragma unroll
        for (int d = 0; d < 32; d++) {
            const ull* row = (const ull*)(scbT + d * 512 + k0);
            const ull r0 = row[0], r1 = row[1], r2 = row[2], r3 = row[3];
            const ull xa = pk2(xvA[d], xvA[d]);
            const ull xb = pk2(xvB[d], xvB[d]);
            aA0 = fma2(r0, xa, aA0); aA1 = fma2(r1, xa, aA1);
            aA2 = fma2(r2, xa, aA2); aA3 = fma2(r3, xa, aA3);
            aB0 = fma2(r0, xb, aB0); aB1 = fma2(r1, xb, aB1);
            aB2 = fma2(r2, xb, aB2); aB3 = fma2(r3, xb, aB3);
        }
        float xcA[8], xcB[8];
        upk2(aA0, xcA[0], xcA[1]); upk2(aA1, xcA[2], xcA[3]);
        upk2(aA2, xcA[4], xcA[5]); upk2(aA3, xcA[6], xcA[7]);
        upk2(aB0, xcB[0], xcB[1]); upk2(aB1, xcB[2], xcB[3]);
        upk2(aB2, xcB[4], xcB[5]); upk2(aB3, xcB[6], xcB[7]);
        #pragma unroll
        for (int j = 0; j < 8; j++) {
            const float c2 = sc2[k0 + j];
            const float dA = __fadd_rn(__fsub_rn(x2A, __fmul_rn(2.0f, xcA[j])), c2);
            const float dB = __fadd_rn(__fsub_rn(x2B, __fmul_rn(2.0f, xcB[j])), c2);
            if (dA < bestA) { bestA = dA; biA = k0 + j; }
            if (dB < bestB) { bestB = dB; biB = k0 + j; }
        }
    }

    float err = 0.0f;
    {
        const float* c = cb + biA * 32;
        float* qb = q + ((size_t)bA * 32) * 4096 + pA;
        #pragma unroll
        for (int d = 0; d < 32; d++) {
            const float e = __fsub_rn(c[d], xvA[d]);
            err = __fadd_rn(err, __fmul_rn(e, e));
            qb[(size_t)d * 4096] = __fadd_rn(xvA[d], e);
        }
        outF[4194304 + vA] = (float)biA;
    }
    {
        const float* c = cb + biB * 32;
        float* qb = q + ((size_t)bB * 32) * 4096 + pB;
        #pragma unroll
        for (int d = 0; d < 32; d++) {
            const float e = __fsub_rn(c[d], xvB[d]);
            err = __fadd_rn(err, __fmul_rn(e, e));
            qb[(size_t)d * 4096] = __fadd_rn(xvB[d], e);
        }
        outF[4194304 + vB] = (float)biB;
    }

    __shared__ float red[256];
    red[t] = err;
    __syncthreads();
    #pragma unroll
    for (int s2 = 128; s2 > 0; s2 >>= 1) {
        if (t < s2) red[t] += red[t + s2];
        __syncthreads();
    }
    if (t == 0) partial[blockIdx.x] = red[0];
}

// ---------------------------------------------------------------------------
// K4: upsample2 + conv3 (32->16) + bias + gelu, PHASE-DECOMPOSED (image-only
// path; re-associated). Each output phase (oy&1, ox&1) is a 2x2-tap conv on
// the q grid with combined weights. Warp-per-phase keeps weight LDS broadcast.
// Tile 32x16 out, 2 px/thread. grid (4,8,B), dyn smem 55872 B.
// ---------------------------------------------------------------------------
__global__ void k4_up_conv3_gelu(const float* __restrict__ q,
                                 const float* __restrict__ w3,
                                 const float* __restrict__ b3,
                                 float* __restrict__ h3) {
    extern __shared__ float sm4[];
    float* qs = sm4;                 // 5760 floats (q tile [32][10][18]); temp for raw w3
    float* cw = sm4 + 5760;          // 8192 floats: [ph][tap][c][oc16]
    float* bs = sm4 + 13952;         // 16

    const int b   = blockIdx.z;
    const int ox0 = blockIdx.x * 32, oy0 = blockIdx.y * 16;
    const int t   = threadIdx.x;

    // stage raw w3 into qs-as-temp
    for (int i = t; i < 4608; i += 256) qs[i] = w3[i];
    if (t < 16) bs[t] = b3[t];
    __syncthreads();

    // combined weights: cw[((ph*4+tap)*32+c)*16+o]
    for (int e = t; e < 8192; e += 256) {
        const int o = e & 15, c = (e >> 4) & 31, tap = (e >> 9) & 3, ph = e >> 11;
        const int tx = tap & 1, ty = tap >> 1, dx = ph & 1, dy = ph >> 1;
        const int ys = dy ? (ty ? 2 : 0) : (ty ? 1 : 0);
        const int yc = dy ? (ty ? 1 : 2) : (ty ? 2 : 1);
        const int xs = dx ? (tx ? 2 : 0) : (tx ? 1 : 0);
        const int xc = dx ? (tx ? 1 : 2) : (tx ? 2 : 1);
        float ssum = 0.0f;
        for (int iy = 0; iy < yc; iy++)
            for (int ix = 0; ix < xc; ix++)
                ssum += qs[o * 288 + c * 9 + (ys + iy) * 3 + (xs + ix)];
        cw[e] = ssum;
    }
    __syncthreads();

    // q tile [32][10][18], zero-filled OOB
    const int qyb = (oy0 >> 1) - 1, qxb = (ox0 >> 1) - 1;
    const float* qb_ = q + (size_t)b * 131072;
    for (int i = t; i < 5760; i += 256) {
        const int c = i / 180, rem = i % 180, r = rem / 18, cc = rem % 18;
        const int gy = qyb + r, gx = qxb + cc;
        float v = 0.0f;
        if (gy >= 0 && gy < 64 && gx >= 0 && gx < 64) v = qb_[c * 4096 + gy * 64 + gx];
        qs[c * 180 + r * 18 + cc] = v;
    }
    __syncthreads();

    const int wrp = t >> 5, lane = t & 31;
    const int dx = wrp & 1, dy = (wrp >> 1) & 1, sub = wrp >> 2;
    const int ph = dy * 2 + dx;
    const int idxA = sub * 32 + lane, idxB = idxA + 64;
    const int uxA = idxA & 15, uyA = idxA >> 4;
    const int uxB = idxB & 15, uyB = idxB >> 4;
    const int jxA = uxA + dx, jyA = uyA + dy;
    const int jxB = uxB + dx, jyB = uyB + dy;

    ull A[8], B[8];
    #pragma unroll
    for (int p = 0; p < 8; p++) { A[p] = 0; B[p] = 0; }

    const float* cwp = cw + ph * 4 * 32 * 16;
    for (int c = 0; c < 32; c++) {
        const float* qc = qs + c * 180;
        const float a00 = qc[jyA * 18 + jxA],       a01 = qc[jyA * 18 + jxA + 1];
        const float a10 = qc[(jyA + 1) * 18 + jxA], a11 = qc[(jyA + 1) * 18 + jxA + 1];
        const float b00 = qc[jyB * 18 + jxB],       b01 = qc[jyB * 18 + jxB + 1];
        const float b10 = qc[(jyB + 1) * 18 + jxB], b11 = qc[(jyB + 1) * 18 + jxB + 1];
        const ull sa[4] = { pk2(a00, a00), pk2(a01, a01), pk2(a10, a10), pk2(a11, a11) };
        const ull sb[4] = { pk2(b00, b00), pk2(b01, b01), pk2(b10, b10), pk2(b11, b11) };
        #pragma unroll
        for (int tap = 0; tap < 4; tap++) {
            const ull* wr = (const ull*)(cwp + (tap * 32 + c) * 16);
            #pragma unroll
            for (int p = 0; p < 8; p++) {
                const ull wv = wr[p];
                A[p] = fma2(wv, sa[tap], A[p]);
                B[p] = fma2(wv, sb[tap], B[p]);
            }
        }
    }

    const int oxA = ox0 + 2 * uxA + dx, oyA = oy0 + 2 * uyA + dy;
    const int oxB = ox0 + 2 * uxB + dx, oyB = oy0 + 2 * uyB + dy;
    #pragma unroll
    for (int p = 0; p < 8; p++) {
        float a0, a1, c0, c1;
        upk2(A[p], a0, a1);
        upk2(B[p], c0, c1);
        h3[(((size_t)b * 16 + 2 * p + 0) * 128 + oyA) * 128 + oxA] = gelu_fast(a0 + bs[2 * p + 0]);
        h3[(((size_t)b * 16 + 2 * p + 1) * 128 + oyA) * 128 + oxA] = gelu_fast(a1 + bs[2 * p + 1]);
        h3[(((size_t)b * 16 + 2 * p + 0) * 128 + oyB) * 128 + oxB] = gelu_fast(c0 + bs[2 * p + 0]);
        h3[(((size_t)b * 16 + 2 * p + 1) * 128 + oyB) * 128 + oxB] = gelu_fast(c1 + bs[2 * p + 1]);
    }
}

// ---------------------------------------------------------------------------
// K5: upsample2 + conv4 (16->1) + clip, PHASE-DECOMPOSED (image-only path).
// Tile 32x32 out, 4 px/thread. grid (8,8,B).
// ---------------------------------------------------------------------------
__global__ void k5_up_conv4_clip(const float* __restrict__ h3,
                                 const float* __restrict__ w4,
                                 const float* __restrict__ b4,
                                 float* __restrict__ outF) {
    __shared__ float hs[16 * 18 * 18];   // 20736 B
    __shared__ float cw5[256];           // [ph][tap][c]
    __shared__ float wtmp[144];

    const int b   = blockIdx.z;
    const int ox0 = blockIdx.x * 32, oy0 = blockIdx.y * 32;
    const int t   = threadIdx.x;

    if (t < 144) wtmp[t] = w4[t];
    __syncthreads();

    {   // combined weights: cw5[ph*64 + tap*16 + c]
        const int c = t & 15, tap = (t >> 4) & 3, ph = t >> 6;
        const int tx = tap & 1, ty = tap >> 1, dx = ph & 1, dy = ph >> 1;
        const int ys = dy ? (ty ? 2 : 0) : (ty ? 1 : 0);
        const int yc = dy ? (ty ? 1 : 2) : (ty ? 2 : 1);
        const int xs = dx ? (tx ? 2 : 0) : (tx ? 1 : 0);
        const int xc = dx ? (tx ? 1 : 2) : (tx ? 2 : 1);
        float ssum = 0.0f;
        for (int iy = 0; iy < yc; iy++)
            for (int ix = 0; ix < xc; ix++)
                ssum += wtmp[c * 9 + (ys + iy) * 3 + (xs + ix)];
        cw5[t] = ssum;
    }

    const int qyb = (oy0 >> 1) - 1, qxb = (ox0 >> 1) - 1;
    const float* hb = h3 + (size_t)b * 16 * 16384;
    for (int i = t; i < 16 * 324; i += 256) {
        const int c = i / 324, rem = i % 324, r = rem / 18, cc = rem % 18;
        const int gy = qyb + r, gx = qxb + cc;
        float v = 0.0f;
        if (gy >= 0 && gy < 128 && gx >= 0 && gx < 128) v = hb[c * 16384 + gy * 128 + gx];
        hs[c * 324 + r * 18 + cc] = v;
    }
    __syncthreads();

    const int wrp = t >> 5, lane = t & 31;
    const int dx = wrp & 1, dy = (wrp >> 1) & 1, sub = wrp >> 2;
    const float* cwp = cw5 + (dy * 2 + dx) * 64;
    const float bias = b4[0];

    int jx[4], jy[4], ox[4], oy[4];
    #pragma unroll
    for (int i = 0; i < 4; i++) {
        const int idx = sub * 32 + lane + 64 * i;   // [0,256)
        const int ux = idx & 15, uy = idx >> 4;
        jx[i] = ux + dx; jy[i] = uy + dy;
        ox[i] = ox0 + 2 * ux + dx; oy[i] = oy0 + 2 * uy + dy;
    }

    float acc[4] = {0.f, 0.f, 0.f, 0.f};
    for (int c = 0; c < 16; c++) {
        const float w00 = cwp[c], w01 = cwp[16 + c], w10 = cwp[32 + c], w11 = cwp[48 + c];
        const float* hc = hs + c * 324;
        #pragma unroll
        for (int i = 0; i < 4; i++) {
            acc[i] = fmaf(hc[jy[i] * 18 + jx[i]],           w00, acc[i]);
            acc[i] = fmaf(hc[jy[i] * 18 + jx[i] + 1],       w01, acc[i]);
            acc[i] = fmaf(hc[(jy[i] + 1) * 18 + jx[i]],     w10, acc[i]);
            acc[i] = fmaf(hc[(jy[i] + 1) * 18 + jx[i] + 1], w11, acc[i]);
        }
    }

    #pragma unroll
    for (int i = 0; i < 4; i++) {
        float a = acc[i] + bias;
        a = fminf(fmaxf(a, -1.0f), 1.0f);
        outF[(size_t)b * 65536 + oy[i] * 256 + ox[i]] = a;
    }
}

// ---------------------------------------------------------------------------
// K6: deterministic final reduction of commit loss (512 partials).
// ---------------------------------------------------------------------------
__global__ void k6_loss(const float* __restrict__ partial, float* __restrict__ outF) {
    __shared__ float red[256];
    const int t = threadIdx.x;
    red[t] = partial[t] + partial[t + 256];
    __syncthreads();
    #pragma unroll
    for (int s2 = 128; s2 > 0; s2 >>= 1) {
        if (t < s2) red[t] += red[t + s2];
        __syncthreads();
    }
    if (t == 0) outF[4194304 + 262144] = red[0] * (1.0f / 8388608.0f);
}

// ---------------------------------------------------------------------------
extern "C" void kernel_launch(void* const* d_in, const int* in_sizes, int n_in,
                              void* d_out, int out_size) {
    const float* x  = (const float*)d_in[0];
    const float* w1 = (const float*)d_in[1];
    const float* b1 = (const float*)d_in[2];
    const float* w2 = (const float*)d_in[3];
    const float* b2 = (const float*)d_in[4];
    const float* cb = (const float*)d_in[5];
    const float* w3 = (const float*)d_in[6];
    const float* b3 = (const float*)d_in[7];
    const float* w4 = (const float*)d_in[8];
    const float* b4 = (const float*)d_in[9];
    float* outF = (float*)d_out;

    float *h1, *h2, *q, *h3, *partial;
    cudaGetSymbolAddress((void**)&h1, g_h1);
    cudaGetSymbolAddress((void**)&h2, g_h2);
    cudaGetSymbolAddress((void**)&q,  g_q);
    cudaGetSymbolAddress((void**)&h3, g_h3);
    cudaGetSymbolAddress((void**)&partial, g_partial);

    cudaFuncSetAttribute(k3_vq, cudaFuncAttributeMaxDynamicSharedMemorySize, 67584);
    cudaFuncSetAttribute(k4_up_conv3_gelu, cudaFuncAttributeMaxDynamicSharedMemorySize, 55872);

    k1_conv1_pool_gelu<<<dim3(8, 8, BATCH), dim3(16, 16)>>>(x, w1, b1, h1);
    k2_conv2_pool<<<dim3(8, 8, BATCH), 256>>>(h1, w2, b2, h2);
    k3_vq<<<512, 256, 67584>>>(h2, cb, q, outF, partial);
    k4_up_conv3_gelu<<<dim3(4, 8, BATCH), 256, 55872>>>(q, w3, b3, h3);
    k5_up_conv4_clip<<<dim3(8, 8, BATCH), 256>>>(h3, w4, b4, outF);
    k6_loss<<<1, 256>>>(partial, outF);
}